// round 1
// baseline (speedup 1.0000x reference)
#include <cuda_runtime.h>

#define Bv 8
#define Av 1024
#define NNv 64
#define Gv 25
#define Fv 128
#define Lv 3
#define AP 8

#define WIDTHc (5.0f/24.0f)
#define COEFFc (-0.5f/(WIDTHc*WIDTHc))
#define LN2c 0.6931471805599453f

// ---------------- scratch (no allocations allowed) ----------------
__device__ float g_y[Bv*Av*Fv];   // in2f output per layer
__device__ float g_v[Bv*Av*Fv];   // cfconv masked-sum output
__device__ float g_r[Bv*Av*NNv]; // pairwise distances

// ---------------- helpers ----------------
__device__ __forceinline__ float ssp(float x) {
    // softplus(x) - ln2, numerically stable
    float e = __expf(-fabsf(x));
    return fmaxf(x, 0.0f) + __logf(1.0f + e) - LN2c;
}

__device__ __forceinline__ unsigned long long fma2(unsigned long long a,
                                                   unsigned long long b,
                                                   unsigned long long c) {
    unsigned long long d;
    asm("fma.rn.f32x2 %0, %1, %2, %3;" : "=l"(d) : "l"(a), "l"(b), "l"(c));
    return d;
}
__device__ __forceinline__ unsigned long long add2(unsigned long long a,
                                                   unsigned long long b) {
    unsigned long long d;
    asm("add.rn.f32x2 %0, %1, %2;" : "=l"(d) : "l"(a), "l"(b));
    return d;
}
__device__ __forceinline__ unsigned long long pack2(float lo, float hi) {
    unsigned long long d;
    asm("mov.b64 %0, {%1, %2};" : "=l"(d) : "f"(lo), "f"(hi));
    return d;
}
__device__ __forceinline__ float hsum2(unsigned long long v) {
    float lo, hi;
    asm("mov.b64 {%0, %1}, %2;" : "=f"(lo), "=f"(hi) : "l"(v));
    return lo + hi;
}

// ---------------- kernel 0: embedding + distances ----------------
__global__ void init_kernel(const int* __restrict__ zA, const float* __restrict__ pos,
                            const float* __restrict__ cell, const float* __restrict__ off,
                            const int* __restrict__ nbr, const float* __restrict__ emb,
                            float* __restrict__ x)
{
    const int atom = blockIdx.x;
    const int t = threadIdx.x;
    const int b = atom >> 10;
    int z = zA[atom];
    x[(size_t)atom*Fv + t] = emb[(size_t)z*Fv + t];
    if (t < NNv) {
        int e = atom*NNv + t;
        int nb = nbr[e];
        const float* pi = pos + (size_t)atom*3;
        const float* pj = pos + (size_t)((b<<10) + nb)*3;
        const float* o  = off + (size_t)e*3;
        const float* c  = cell + b*9;
        float dx = pj[0]-pi[0] + o[0]*c[0] + o[1]*c[3] + o[2]*c[6];
        float dy = pj[1]-pi[1] + o[0]*c[1] + o[1]*c[4] + o[2]*c[7];
        float dz = pj[2]-pi[2] + o[0]*c[2] + o[1]*c[5] + o[2]*c[8];
        float d2 = dx*dx + dy*dy + dz*dz;
        g_r[e] = (d2 > 0.0f) ? sqrtf(d2) : 0.0f;
    }
}

// ---------------- kernel 1: y = x @ in2f_w[l] (no bias) ----------------
__global__ __launch_bounds__(256)
void in2f_kernel(const float* __restrict__ x, const float* __restrict__ W)
{
    __shared__ float4 Xs[32][32];
    const int tid = threadIdx.x;
    const int f = tid & 127, half = tid >> 7;
    const int row0 = blockIdx.x * 32;

    for (int i = tid; i < 32*32; i += 256)
        ((float4*)Xs)[i] = ((const float4*)(x + (size_t)row0*Fv))[i];
    __syncthreads();

    float acc[16];
    #pragma unroll
    for (int i = 0; i < 16; ++i) acc[i] = 0.0f;

    for (int k4 = 0; k4 < 32; ++k4) {
        float w0 = W[(4*k4+0)*Fv + f];
        float w1 = W[(4*k4+1)*Fv + f];
        float w2 = W[(4*k4+2)*Fv + f];
        float w3 = W[(4*k4+3)*Fv + f];
        #pragma unroll
        for (int i = 0; i < 16; ++i) {
            float4 xv = Xs[half*16+i][k4];
            acc[i] = fmaf(xv.x,w0,fmaf(xv.y,w1,fmaf(xv.z,w2,fmaf(xv.w,w3,acc[i]))));
        }
    }
    #pragma unroll
    for (int i = 0; i < 16; ++i)
        g_y[(size_t)(row0 + half*16 + i)*Fv + f] = acc[i];
}

// ---------------- kernel 2: fused filter-net + cfconv sum ----------------
// one block : AP atoms. fw2 column and fw1 column cached in registers,
// h in shared (broadcast reads), packed f32x2 FMA on the 128-deep dot.
__global__ __launch_bounds__(256, 2)
void edge_kernel(const float* __restrict__ fw1, const float* __restrict__ fb1,
                 const float* __restrict__ fw2, const float* __restrict__ fb2,
                 const int* __restrict__ neighbors, const float* __restrict__ mask)
{
    __shared__ __align__(16) float s_hs[NNv*Fv];   // 32 KB
    __shared__ float s_fs[NNv][28];                // gaussians
    __shared__ float s_m[NNv], s_v[Fv];
    __shared__ int   s_nb[NNv];

    const int tid  = threadIdx.x;
    const int f    = tid & 127;     // feature column
    const int half = tid >> 7;      // k-range: [0,64) or [64,128)

    // per-layer weights -> registers (reused for AP atoms x 64 neighbors)
    unsigned long long wp[32];
    #pragma unroll
    for (int j = 0; j < 32; ++j) {
        float wa = fw2[(half*64 + 2*j    )*Fv + f];
        float wb = fw2[(half*64 + 2*j + 1)*Fv + f];
        wp[j] = pack2(wa, wb);
    }
    float rw1[Gv];
    #pragma unroll
    for (int g = 0; g < Gv; ++g) rw1[g] = fw1[g*Fv + f];
    const float b1 = fb1[f];
    const float b2 = half ? 0.0f : fb2[f];   // bias counted once across halves

    for (int ai = 0; ai < AP; ++ai) {
        const int atom = blockIdx.x * AP + ai;
        const float* yb = g_y + (size_t)((atom >> 10) << 10) * Fv;

        if (tid < NNv) {
            s_nb[tid] = neighbors[atom*NNv + tid];
            s_m[tid]  = mask[atom*NNv + tid];
            float r = g_r[atom*NNv + tid];
            #pragma unroll
            for (int g = 0; g < Gv; ++g) {
                float d = r - (float)g * WIDTHc;
                s_fs[tid][g] = __expf(COEFFc * d * d);
            }
        }
        __syncthreads();

        // step 1: h[n][f] = ssp(f_ij[n] . fw1[:,f] + fb1[f]); each half does 32 n
        {
            const int n0 = half * 32;
            #pragma unroll 4
            for (int n = n0; n < n0 + 32; ++n) {
                float acc = b1;
                #pragma unroll
                for (int g = 0; g < Gv; ++g) acc = fmaf(s_fs[n][g], rw1[g], acc);
                s_hs[n*Fv + f] = ssp(acc);
            }
        }
        __syncthreads();

        // step 2: v[f] = sum_n m_n * y[nb_n][f] * (h[n] . fw2[:,f] + fb2[f])
        float vacc = 0.0f;
        for (int n = 0; n < NNv; ++n) {
            const ulonglong2* hp = (const ulonglong2*)(s_hs + n*Fv + half*64);
            float yv = yb[(size_t)s_nb[n]*Fv + f];
            float mn = s_m[n];
            unsigned long long a0 = 0ull, a1 = 0ull, a2 = 0ull, a3 = 0ull;
            #pragma unroll
            for (int j = 0; j < 16; j += 2) {
                ulonglong2 u  = hp[j];
                ulonglong2 v2 = hp[j+1];
                a0 = fma2(u.x,  wp[2*j+0], a0);
                a1 = fma2(u.y,  wp[2*j+1], a1);
                a2 = fma2(v2.x, wp[2*j+2], a2);
                a3 = fma2(v2.y, wp[2*j+3], a3);
            }
            float p = hsum2(add2(add2(a0, a1), add2(a2, a3))) + b2;
            vacc = fmaf(mn * yv, p, vacc);
        }

        if (half == 0) s_v[f] = vacc;
        __syncthreads();
        if (half == 1) g_v[(size_t)atom*Fv + f] = vacc + s_v[f];
        // no extra barrier needed: next iteration's smem writes are fenced by
        // the post-gaussian / post-step1 barriers before any re-read.
        __syncthreads();
    }
}

// ---------------- kernel 3: x += dense(ssp(f2out(v))) ----------------
__global__ __launch_bounds__(256)
void post_kernel(const float* __restrict__ W1, const float* __restrict__ B1,
                 const float* __restrict__ W2, const float* __restrict__ B2,
                 float* __restrict__ x)
{
    __shared__ float4 Vs[16][32];
    __shared__ float4 Ts[16][32];
    const int tid = threadIdx.x;
    const int f = tid & 127, half = tid >> 7;
    const int row0 = blockIdx.x * 16;

    for (int i = tid; i < 16*32; i += 256)
        ((float4*)Vs)[i] = ((const float4*)(g_v + (size_t)row0*Fv))[i];
    __syncthreads();

    float acc[8];
    #pragma unroll
    for (int i = 0; i < 8; ++i) acc[i] = 0.0f;
    for (int k4 = 0; k4 < 32; ++k4) {
        float w0 = W1[(4*k4+0)*Fv + f];
        float w1 = W1[(4*k4+1)*Fv + f];
        float w2 = W1[(4*k4+2)*Fv + f];
        float w3 = W1[(4*k4+3)*Fv + f];
        #pragma unroll
        for (int i = 0; i < 8; ++i) {
            float4 xv = Vs[half*8+i][k4];
            acc[i] = fmaf(xv.x,w0,fmaf(xv.y,w1,fmaf(xv.z,w2,fmaf(xv.w,w3,acc[i]))));
        }
    }
    float b1v = B1[f];
    #pragma unroll
    for (int i = 0; i < 8; ++i)
        ((float*)Ts)[(half*8+i)*Fv + f] = ssp(acc[i] + b1v);
    __syncthreads();

    float acc2[8];
    #pragma unroll
    for (int i = 0; i < 8; ++i) acc2[i] = 0.0f;
    for (int k4 = 0; k4 < 32; ++k4) {
        float w0 = W2[(4*k4+0)*Fv + f];
        float w1 = W2[(4*k4+1)*Fv + f];
        float w2 = W2[(4*k4+2)*Fv + f];
        float w3 = W2[(4*k4+3)*Fv + f];
        #pragma unroll
        for (int i = 0; i < 8; ++i) {
            float4 tv = Ts[half*8+i][k4];
            acc2[i] = fmaf(tv.x,w0,fmaf(tv.y,w1,fmaf(tv.z,w2,fmaf(tv.w,w3,acc2[i]))));
        }
    }
    float b2v = B2[f];
    #pragma unroll
    for (int i = 0; i < 8; ++i) {
        size_t idx = (size_t)(row0 + half*8 + i)*Fv + f;
        x[idx] += acc2[i] + b2v;
    }
}

// ---------------- launcher ----------------
extern "C" void kernel_launch(void* const* d_in, const int* in_sizes, int n_in,
                              void* d_out, int out_size)
{
    const int*   zA   = (const int*)  d_in[0];
    const float* pos  = (const float*)d_in[1];
    const float* cell = (const float*)d_in[2];
    const float* off  = (const float*)d_in[3];
    const int*   nbr  = (const int*)  d_in[4];
    const float* msk  = (const float*)d_in[5];
    const float* emb  = (const float*)d_in[6];
    const float* fw1  = (const float*)d_in[7];
    const float* fb1  = (const float*)d_in[8];
    const float* fw2  = (const float*)d_in[9];
    const float* fb2  = (const float*)d_in[10];
    const float* i2f  = (const float*)d_in[11];
    const float* f2o  = (const float*)d_in[12];
    const float* f2ob = (const float*)d_in[13];
    const float* dw   = (const float*)d_in[14];
    const float* db   = (const float*)d_in[15];
    float* x = (float*)d_out;   // x lives in d_out across all layers

    init_kernel<<<Bv*Av, Fv>>>(zA, pos, cell, off, nbr, emb, x);
    for (int l = 0; l < Lv; ++l) {
        in2f_kernel<<<(Bv*Av)/32, 256>>>(x, i2f + (size_t)l*Fv*Fv);
        edge_kernel<<<(Bv*Av)/AP, 256>>>(fw1 + (size_t)l*Gv*Fv, fb1 + (size_t)l*Fv,
                                         fw2 + (size_t)l*Fv*Fv, fb2 + (size_t)l*Fv,
                                         nbr, msk);
        post_kernel<<<(Bv*Av)/16, 256>>>(f2o + (size_t)l*Fv*Fv, f2ob + (size_t)l*Fv,
                                         dw  + (size_t)l*Fv*Fv, db   + (size_t)l*Fv, x);
    }
}

// round 4
// speedup vs baseline: 3.9860x; 3.9860x over previous
#include <cuda_runtime.h>
#include <cuda_bf16.h>
#include <cstdint>

#define Bv 8
#define Av 1024
#define NNv 64
#define Gv 25
#define Fv 128
#define Lv 3
#define NBT 2048            // big-tiles: 4 atoms / 256 edges each
#define EDGE_GRID 152

#define WIDTHc (5.0f/24.0f)
#define COEFFc (-0.5f/(WIDTHc*WIDTHc))
#define LN2c 0.6931471805599453f

// ---- dynamic smem offsets (bytes) for edge kernel ----
#define OFF_YT   0          // bf16 [256 e][136]  stride 272B   (69632 B)
#define OFF_FW2T 69632      // bf16 [128 f][152]  stride 304B   (38912 B)
#define OFF_FB1  108544     // f32 [128]
#define OFF_SR   109056     // f32 [256]
#define OFF_SM   110080     // f32 [256]
#define OFF_VSM  111104     // f32 [8][128]
#define SMEM_EDGE 115200

// ---------------- scratch ----------------
__device__ __nv_bfloat16 g_y[Bv*Av*Fv];
__device__ float g_v[Bv*Av*Fv];
__device__ float g_r[Bv*Av*NNv];

// ---------------- helpers ----------------
__device__ __forceinline__ float ssp(float x) {
    // softplus(x)-ln2, 1 MUFU: u=e^{-|x|}, ln(1+u) via A&S 4.1.43 poly
    float u = __expf(-fabsf(x));
    float p = u*(0.99949556f + u*(-0.49190896f + u*(0.28947478f
              + u*(-0.13606275f + u*0.03215845f))));
    return fmaxf(x, 0.0f) + p - LN2c;
}
__device__ __forceinline__ uint32_t s2u(const void* p) {
    uint32_t a;
    asm("{ .reg .u64 t; cvta.to.shared.u64 t, %1; cvt.u32.u64 %0, t; }" : "=r"(a) : "l"(p));
    return a;
}
__device__ __forceinline__ uint32_t bf16pk(float lo, float hi) {
    uint32_t r;
    asm("cvt.rn.bf16x2.f32 %0, %1, %2;" : "=r"(r) : "f"(hi), "f"(lo));
    return r;
}
__device__ __forceinline__ float2 bf2f(uint32_t p) {
    float2 r;
    r.x = __uint_as_float(p << 16);
    r.y = __uint_as_float(p & 0xffff0000u);
    return r;
}
__device__ __forceinline__ void mma_bf16(float* d, const uint32_t* a, const uint32_t* b) {
    asm volatile(
        "mma.sync.aligned.m16n8k16.row.col.f32.bf16.bf16.f32 "
        "{%0,%1,%2,%3}, {%4,%5,%6,%7}, {%8,%9}, {%0,%1,%2,%3};"
        : "+f"(d[0]), "+f"(d[1]), "+f"(d[2]), "+f"(d[3])
        : "r"(a[0]), "r"(a[1]), "r"(a[2]), "r"(a[3]), "r"(b[0]), "r"(b[1]));
}
__device__ __forceinline__ void cp16(uint32_t dst, const void* src) {
    asm volatile("cp.async.ca.shared.global [%0], [%1], 16;" :: "r"(dst), "l"(src) : "memory");
}

// ---------------- kernel 0: embedding + distances ----------------
__global__ void init_kernel(const int* __restrict__ zA, const float* __restrict__ pos,
                            const float* __restrict__ cell, const float* __restrict__ off,
                            const int* __restrict__ nbr, const float* __restrict__ emb,
                            float* __restrict__ x)
{
    const int atom = blockIdx.x;
    const int t = threadIdx.x;
    const int b = atom >> 10;
    int z = zA[atom];
    x[(size_t)atom*Fv + t] = emb[(size_t)z*Fv + t];
    if (t < NNv) {
        int e = atom*NNv + t;
        int nb = nbr[e];
        const float* pi = pos + (size_t)atom*3;
        const float* pj = pos + (size_t)((b<<10) + nb)*3;
        const float* o  = off + (size_t)e*3;
        const float* c  = cell + b*9;
        float dx = pj[0]-pi[0] + o[0]*c[0] + o[1]*c[3] + o[2]*c[6];
        float dy = pj[1]-pi[1] + o[0]*c[1] + o[1]*c[4] + o[2]*c[7];
        float dz = pj[2]-pi[2] + o[0]*c[2] + o[1]*c[5] + o[2]*c[8];
        float d2 = dx*dx + dy*dy + dz*dz;
        g_r[e] = (d2 > 0.0f) ? sqrtf(d2) : 0.0f;
    }
}

// ---------------- kernel 1: y = x @ in2f_w[l] -> bf16 ----------------
__global__ __launch_bounds__(256)
void in2f_kernel(const float* __restrict__ x, const float* __restrict__ W)
{
    __shared__ float4 Xs[32][32];
    const int tid = threadIdx.x;
    const int f = tid & 127, half = tid >> 7;
    const int row0 = blockIdx.x * 32;

    for (int i = tid; i < 32*32; i += 256)
        ((float4*)Xs)[i] = ((const float4*)(x + (size_t)row0*Fv))[i];
    __syncthreads();

    float acc[16];
    #pragma unroll
    for (int i = 0; i < 16; ++i) acc[i] = 0.0f;

    for (int k4 = 0; k4 < 32; ++k4) {
        float w0 = W[(4*k4+0)*Fv + f];
        float w1 = W[(4*k4+1)*Fv + f];
        float w2 = W[(4*k4+2)*Fv + f];
        float w3 = W[(4*k4+3)*Fv + f];
        #pragma unroll
        for (int i = 0; i < 16; ++i) {
            float4 xv = Xs[half*16+i][k4];
            acc[i] = fmaf(xv.x,w0,fmaf(xv.y,w1,fmaf(xv.z,w2,fmaf(xv.w,w3,acc[i]))));
        }
    }
    #pragma unroll
    for (int i = 0; i < 16; ++i)
        g_y[(size_t)(row0 + half*16 + i)*Fv + f] = __float2bfloat16(acc[i]);
}

// ---------------- kernel 2: mma.sync fused filter-net + cfconv ----------------
// Big-tile = 4 atoms = 256 edges. Warp w owns edges [32w, 32w+32) (2 M-tiles).
// GEMM1: H = ssp(Fij@fw1 + fb1)*m_e, packed to A-fragments in registers.
// Virtual col k=128: H[:,128]=m_e, fw2T[:,128]=fb2 (folds mask-sum * fb2).
// GEMM2: acc2 = H @ fw2T; epilogue v[f] = sum_e acc2[e][f]*y[nb_e][f].
__global__ __launch_bounds__(256, 1)
void edge_mma_kernel(const float* __restrict__ fw1, const float* __restrict__ fb1,
                     const float* __restrict__ fw2, const float* __restrict__ fb2,
                     const int* __restrict__ nbr, const float* __restrict__ msk)
{
    extern __shared__ __align__(16) char sm[];
    __nv_bfloat16* YT   = (__nv_bfloat16*)(sm + OFF_YT);     // [256][136]
    __nv_bfloat16* FW2T = (__nv_bfloat16*)(sm + OFF_FW2T);   // [128][152]
    float* FB1 = (float*)(sm + OFF_FB1);
    float* SR  = (float*)(sm + OFF_SR);
    float* SMk = (float*)(sm + OFF_SM);
    float* VSM = (float*)(sm + OFF_VSM);

    const int t    = threadIdx.x;
    const int w    = t >> 5;
    const int lane = t & 31;
    const int qr   = lane >> 2;   // 0..7
    const int qc   = lane & 3;    // 0..3
    const uint32_t yt_base = s2u(YT);

    // ---- per-layer setup ----
    if (t < 128) FB1[t] = fb1[t];
    {   // fw2^T -> smem [f][k], virtual col 128 = fb2, 129..151 = 0
        const int f = t >> 1;
        const int k0 = (t & 1) * 64;
        for (int k = 0; k < 64; ++k)
            FW2T[f*152 + k0 + k] = __float2bfloat16(fw2[(k0 + k)*Fv + f]);
        if (t & 1) {
            FW2T[f*152 + 128] = __float2bfloat16(fb2[f]);
            for (int k = 129; k < 152; ++k) FW2T[f*152 + k] = __float2bfloat16(0.0f);
        }
    }
    // fw1 B-fragments: [kstep s][ntile n][2]
    uint32_t b1f[2][16][2];
    #pragma unroll
    for (int s = 0; s < 2; ++s) {
        #pragma unroll
        for (int n = 0; n < 16; ++n) {
            int g = 2*qc + 16*s;
            int fn = 8*n + qr;
            float w00 = (g   < Gv) ? fw1[(g  )*Fv + fn] : 0.0f;
            float w01 = (g+1 < Gv) ? fw1[(g+1)*Fv + fn] : 0.0f;
            float w10 = (g+8 < Gv) ? fw1[(g+8)*Fv + fn] : 0.0f;
            float w11 = (g+9 < Gv) ? fw1[(g+9)*Fv + fn] : 0.0f;
            b1f[s][n][0] = bf16pk(w00, w01);
            b1f[s][n][1] = bf16pk(w10, w11);
        }
    }
    __syncthreads();

    for (int bt = blockIdx.x; bt < NBT; bt += gridDim.x) {
        const int e0 = bt * 256;
        // ---- stage y rows (bf16) via cp.async; one row per thread ----
        {
            int nb = __ldg(nbr + e0 + t);
            int batch = (e0 + t) >> 16;
            const __nv_bfloat16* src = g_y + ((size_t)batch << 17) + (size_t)nb * Fv;
            uint32_t dst = yt_base + (uint32_t)t * 272u;
            #pragma unroll
            for (int j = 0; j < 8; ++j)
                cp16(dst + 16u*j, (const char*)src + 16*j);
            asm volatile("cp.async.commit_group;" ::: "memory");
            #pragma unroll
            for (int j = 8; j < 16; ++j)
                cp16(dst + 16u*j, (const char*)src + 16*j);
            asm volatile("cp.async.commit_group;" ::: "memory");
            SR[t]  = g_r[e0 + t];
            SMk[t] = msk[e0 + t];
        }
        __syncthreads();

        // ---- GEMM1 -> A2 fragments (registers only) ----
        uint32_t A2[2][9][4];
        #pragma unroll
        for (int Mt = 0; Mt < 2; ++Mt) {
            const int r0 = 32*w + 16*Mt + qr;
            const int r1 = r0 + 8;
            const float rr0 = SR[r0], rr1 = SR[r1];
            const float m0 = SMk[r0], m1 = SMk[r1];

            uint32_t Af[2][4];
            #pragma unroll
            for (int s = 0; s < 2; ++s) {
                const int g = 2*qc + 16*s;
                float d, e00, e01, e02, e03, e10, e11, e12, e13;
                d = rr0 - (g  )*WIDTHc; e00 = (g   < Gv) ? __expf(COEFFc*d*d) : 0.0f;
                d = rr0 - (g+1)*WIDTHc; e01 = (g+1 < Gv) ? __expf(COEFFc*d*d) : 0.0f;
                d = rr0 - (g+8)*WIDTHc; e02 = (g+8 < Gv) ? __expf(COEFFc*d*d) : 0.0f;
                d = rr0 - (g+9)*WIDTHc; e03 = (g+9 < Gv) ? __expf(COEFFc*d*d) : 0.0f;
                d = rr1 - (g  )*WIDTHc; e10 = (g   < Gv) ? __expf(COEFFc*d*d) : 0.0f;
                d = rr1 - (g+1)*WIDTHc; e11 = (g+1 < Gv) ? __expf(COEFFc*d*d) : 0.0f;
                d = rr1 - (g+8)*WIDTHc; e12 = (g+8 < Gv) ? __expf(COEFFc*d*d) : 0.0f;
                d = rr1 - (g+9)*WIDTHc; e13 = (g+9 < Gv) ? __expf(COEFFc*d*d) : 0.0f;
                Af[s][0] = bf16pk(e00, e01);
                Af[s][1] = bf16pk(e10, e11);
                Af[s][2] = bf16pk(e02, e03);
                Af[s][3] = bf16pk(e12, e13);
            }

            // per k-pair: 2 n-tiles -> one A2 k-step fragment
            #pragma unroll
            for (int s2 = 0; s2 < 8; ++s2) {
                #pragma unroll
                for (int nn = 0; nn < 2; ++nn) {
                    const int n = 2*s2 + nn;
                    float acc[4] = {0.0f, 0.0f, 0.0f, 0.0f};
                    mma_bf16(acc, Af[0], b1f[0][n]);
                    mma_bf16(acc, Af[1], b1f[1][n]);
                    float bA = FB1[8*n + 2*qc];
                    float bB = FB1[8*n + 2*qc + 1];
                    float h0 = ssp(acc[0] + bA) * m0;
                    float h1 = ssp(acc[1] + bB) * m0;
                    float h2 = ssp(acc[2] + bA) * m1;
                    float h3 = ssp(acc[3] + bB) * m1;
                    A2[Mt][s2][2*nn    ] = bf16pk(h0, h1);
                    A2[Mt][s2][2*nn + 1] = bf16pk(h2, h3);
                }
            }
            // virtual k=128 col (mask): k-pair (128,129) lives on qc==0 lanes
            A2[Mt][8][0] = (qc == 0) ? bf16pk(m0, 0.0f) : 0u;
            A2[Mt][8][1] = (qc == 0) ? bf16pk(m1, 0.0f) : 0u;
            A2[Mt][8][2] = 0u;
            A2[Mt][8][3] = 0u;
        }

        asm volatile("cp.async.wait_group 0;" ::: "memory");
        __syncthreads();

        // ---- GEMM2 + epilogue over 4 f-chunks of 32 ----
        #pragma unroll
        for (int ch = 0; ch < 4; ++ch) {
            float acc2[2][4][4];
            #pragma unroll
            for (int Mt = 0; Mt < 2; ++Mt)
                #pragma unroll
                for (int n = 0; n < 4; ++n)
                    #pragma unroll
                    for (int i = 0; i < 4; ++i) acc2[Mt][n][i] = 0.0f;

            #pragma unroll
            for (int s = 0; s < 9; ++s) {
                #pragma unroll
                for (int n = 0; n < 4; ++n) {
                    int fB = 32*ch + 8*n + qr;
                    int k0 = 16*s + 2*qc;
                    uint32_t bb[2];
                    bb[0] = *(const uint32_t*)(FW2T + fB*152 + k0);
                    bb[1] = *(const uint32_t*)(FW2T + fB*152 + k0 + 8);
                    mma_bf16(acc2[0][n], A2[0][s], bb);
                    mma_bf16(acc2[1][n], A2[1][s], bb);
                }
            }

            float vp[8];
            #pragma unroll
            for (int i = 0; i < 8; ++i) vp[i] = 0.0f;
            #pragma unroll
            for (int Mt = 0; Mt < 2; ++Mt) {
                const int rl = 32*w + 16*Mt + qr;
                #pragma unroll
                for (int n = 0; n < 4; ++n) {
                    int fc = 32*ch + 8*n + 2*qc;
                    uint32_t y0 = *(const uint32_t*)(YT + rl*136 + fc);
                    uint32_t y1 = *(const uint32_t*)(YT + (rl+8)*136 + fc);
                    float2 f0 = bf2f(y0);
                    float2 f1 = bf2f(y1);
                    vp[2*n]   = fmaf(acc2[Mt][n][0], f0.x, fmaf(acc2[Mt][n][2], f1.x, vp[2*n]));
                    vp[2*n+1] = fmaf(acc2[Mt][n][1], f0.y, fmaf(acc2[Mt][n][3], f1.y, vp[2*n+1]));
                }
            }
            // reduce across qr groups (same qc)
            #pragma unroll
            for (int i = 0; i < 8; ++i) {
                vp[i] += __shfl_xor_sync(0xffffffffu, vp[i], 4);
                vp[i] += __shfl_xor_sync(0xffffffffu, vp[i], 8);
                vp[i] += __shfl_xor_sync(0xffffffffu, vp[i], 16);
            }
            if (lane < 4) {
                #pragma unroll
                for (int n = 0; n < 4; ++n) {
                    VSM[w*128 + 32*ch + 8*n + 2*lane    ] = vp[2*n];
                    VSM[w*128 + 32*ch + 8*n + 2*lane + 1] = vp[2*n+1];
                }
            }
        }
        __syncthreads();

        // ---- combine warp pairs -> g_v ----
        {
            int f = t & 127;
            int a0 = t >> 7;
            #pragma unroll
            for (int a = 0; a < 2; ++a) {
                int atom = a0 + 2*a;
                g_v[(size_t)(4*bt + atom)*Fv + f] =
                    VSM[(2*atom)*128 + f] + VSM[(2*atom+1)*128 + f];
            }
        }
        __syncthreads();
    }
}

// ---------------- kernel 3: x += dense(ssp(f2out(v))) ----------------
__global__ __launch_bounds__(256)
void post_kernel(const float* __restrict__ W1, const float* __restrict__ B1,
                 const float* __restrict__ W2, const float* __restrict__ B2,
                 float* __restrict__ x)
{
    __shared__ float4 Vs[16][32];
    __shared__ float4 Ts[16][32];
    const int tid = threadIdx.x;
    const int f = tid & 127, half = tid >> 7;
    const int row0 = blockIdx.x * 16;

    for (int i = tid; i < 16*32; i += 256)
        ((float4*)Vs)[i] = ((const float4*)(g_v + (size_t)row0*Fv))[i];
    __syncthreads();

    float acc[8];
    #pragma unroll
    for (int i = 0; i < 8; ++i) acc[i] = 0.0f;
    for (int k4 = 0; k4 < 32; ++k4) {
        float w0 = W1[(4*k4+0)*Fv + f];
        float w1 = W1[(4*k4+1)*Fv + f];
        float w2 = W1[(4*k4+2)*Fv + f];
        float w3 = W1[(4*k4+3)*Fv + f];
        #pragma unroll
        for (int i = 0; i < 8; ++i) {
            float4 xv = Vs[half*8+i][k4];
            acc[i] = fmaf(xv.x,w0,fmaf(xv.y,w1,fmaf(xv.z,w2,fmaf(xv.w,w3,acc[i]))));
        }
    }
    float b1v = B1[f];
    #pragma unroll
    for (int i = 0; i < 8; ++i)
        ((float*)Ts)[(half*8+i)*Fv + f] = ssp(acc[i] + b1v);
    __syncthreads();

    float acc2[8];
    #pragma unroll
    for (int i = 0; i < 8; ++i) acc2[i] = 0.0f;
    for (int k4 = 0; k4 < 32; ++k4) {
        float w0 = W2[(4*k4+0)*Fv + f];
        float w1 = W2[(4*k4+1)*Fv + f];
        float w2 = W2[(4*k4+2)*Fv + f];
        float w3 = W2[(4*k4+3)*Fv + f];
        #pragma unroll
        for (int i = 0; i < 8; ++i) {
            float4 tv = Ts[half*8+i][k4];
            acc2[i] = fmaf(tv.x,w0,fmaf(tv.y,w1,fmaf(tv.z,w2,fmaf(tv.w,w3,acc2[i]))));
        }
    }
    float b2v = B2[f];
    #pragma unroll
    for (int i = 0; i < 8; ++i) {
        size_t idx = (size_t)(row0 + half*8 + i)*Fv + f;
        x[idx] += acc2[i] + b2v;
    }
}

// ---------------- launcher ----------------
extern "C" void kernel_launch(void* const* d_in, const int* in_sizes, int n_in,
                              void* d_out, int out_size)
{
    const int*   zA   = (const int*)  d_in[0];
    const float* pos  = (const float*)d_in[1];
    const float* cell = (const float*)d_in[2];
    const float* off  = (const float*)d_in[3];
    const int*   nbr  = (const int*)  d_in[4];
    const float* msk  = (const float*)d_in[5];
    const float* emb  = (const float*)d_in[6];
    const float* fw1  = (const float*)d_in[7];
    const float* fb1  = (const float*)d_in[8];
    const float* fw2  = (const float*)d_in[9];
    const float* fb2  = (const float*)d_in[10];
    const float* i2f  = (const float*)d_in[11];
    const float* f2o  = (const float*)d_in[12];
    const float* f2ob = (const float*)d_in[13];
    const float* dw   = (const float*)d_in[14];
    const float* db   = (const float*)d_in[15];
    float* x = (float*)d_out;

    cudaFuncSetAttribute(edge_mma_kernel,
                         cudaFuncAttributeMaxDynamicSharedMemorySize, SMEM_EDGE);

    init_kernel<<<Bv*Av, Fv>>>(zA, pos, cell, off, nbr, emb, x);
    for (int l = 0; l < Lv; ++l) {
        in2f_kernel<<<(Bv*Av)/32, 256>>>(x, i2f + (size_t)l*Fv*Fv);
        edge_mma_kernel<<<EDGE_GRID, 256, SMEM_EDGE>>>(
            fw1 + (size_t)l*Gv*Fv, fb1 + (size_t)l*Fv,
            fw2 + (size_t)l*Fv*Fv, fb2 + (size_t)l*Fv, nbr, msk);
        post_kernel<<<(Bv*Av)/16, 256>>>(f2o + (size_t)l*Fv*Fv, f2ob + (size_t)l*Fv,
                                         dw  + (size_t)l*Fv*Fv, db   + (size_t)l*Fv, x);
    }
}